// round 16
// baseline (speedup 1.0000x reference)
#include <cuda_runtime.h>
#include <cuda_bf16.h>

typedef unsigned long long u64;
typedef unsigned int u32;
typedef __nv_bfloat16 bf16;

// ================= scratch (device globals; no allocation) =================
__device__ bf16 g_x_h [1024u*12544], g_x_l [1024u*12544];
__device__ bf16 g_rx_h[4096u*12544], g_rx_l[4096u*12544];
__device__ bf16 g_qW1_h[1024u*12544], g_qW1_l[1024u*12544];
__device__ bf16 g_iW1_h[1024u*12544], g_iW1_l[1024u*12544];
__device__ bf16 g_qW2_h[1024u*1024], g_qW2_l[1024u*1024];
__device__ bf16 g_iW2_h[1024u*1024], g_iW2_l[1024u*1024];
// permuted (gate-interleaved) LSTM weights
__device__ bf16 g_Wih1_h[4096u*1024], g_Wih1_l[4096u*1024];
__device__ bf16 g_Whh1_h[4096u*1024], g_Whh1_l[4096u*1024];
__device__ bf16 g_Wih2_h[4096u*1024], g_Wih2_l[4096u*1024];
__device__ bf16 g_Whh2_h[4096u*1024], g_Whh2_l[4096u*1024];
__device__ float g_bs1[4096], g_bs2[4096];
// split-K partials for layer 1 (combined 5120 rows: q 0..1023, i 1024..5119)
__device__ float g_p0[5120u*1024], g_p1[5120u*1024];
__device__ float g_p2[5120u*1024], g_p3[5120u*1024];
__device__ bf16 g_q1_h[1024u*1024], g_q1_l[1024u*1024];
__device__ bf16 g_r1_h[4096u*1024], g_r1_l[4096u*1024];
__device__ bf16 g_r_h [4096u*1024], g_r_l [4096u*1024];
__device__ bf16 g_h1_h[2][512u*1024], g_h1_l[2][512u*1024];   // double-buffered
__device__ bf16 g_h2_h[2][512u*1024], g_h2_l[2][512u*1024];   // double-buffered
__device__ float g_q  [1024u*1024];
__device__ float g_xp [4096ull*4096];
__device__ float g_c1[512u*1024], g_c2[512u*1024], g_h2f[512u*1024];

// ================= PTX helpers (baseline sm_80+ PTX only) =================
__device__ __forceinline__ u32 smem_u32(const void* p) {
    u32 a;
    asm("{ .reg .u64 t; cvta.to.shared.u64 t, %1; cvt.u32.u64 %0, t; }" : "=r"(a) : "l"(p));
    return a;
}
#define SW128(o) ((o) ^ (((o) >> 3) & 0x70))

__device__ __forceinline__ void cp16(u32 dst, const void* src) {
    asm volatile("cp.async.cg.shared.global [%0], [%1], 16;" :: "r"(dst), "l"(src));
}
#define CP_COMMIT()  asm volatile("cp.async.commit_group;" ::: "memory")
#define CP_WAIT(n)   asm volatile("cp.async.wait_group %0;" :: "n"(n) : "memory")

__device__ __forceinline__ void ldm_x4(u32& r0, u32& r1, u32& r2, u32& r3, u32 addr) {
    asm volatile("ldmatrix.sync.aligned.m8n8.x4.shared.b16 {%0,%1,%2,%3}, [%4];"
                 : "=r"(r0), "=r"(r1), "=r"(r2), "=r"(r3) : "r"(addr));
}
__device__ __forceinline__ void mma_bf16(float* d, const u32* a, const u32* b) {
    asm volatile("mma.sync.aligned.m16n8k16.row.col.f32.bf16.bf16.f32 "
                 "{%0,%1,%2,%3}, {%4,%5,%6,%7}, {%8,%9}, {%0,%1,%2,%3};"
                 : "+f"(d[0]), "+f"(d[1]), "+f"(d[2]), "+f"(d[3])
                 : "r"(a[0]), "r"(a[1]), "r"(a[2]), "r"(a[3]), "r"(b[0]), "r"(b[1]));
}

__device__ __forceinline__ float sigf(float x) {
    return __fdividef(1.0f, 1.0f + __expf(-x));
}
__device__ __forceinline__ float tanhfa(float x) {
    return __fdividef(2.0f, 1.0f + __expf(-2.0f * x)) - 1.0f;
}

static const int SMEM_GEMM = 196608;   // 3 x 64KB stages

// ================= GEMM machinery (R14 config, unchanged) =================
__device__ __forceinline__ void load_stage128(
    u32 base,
    const bf16* __restrict__ Ah, const bf16* __restrict__ Al,
    const bf16* __restrict__ Bh, const bf16* __restrict__ Bl,
    int Ks, int m0, int n0, int k0, int tid)
{
#pragma unroll
    for (int i = 0; i < 4; ++i) {
        int u = tid + i * 256;
        int row = u >> 3, cu = u & 7;
        u32 so = SW128((u32)(row * 128 + cu * 16));
        size_t ao = (size_t)(m0 + row) * Ks + k0 + cu * 8;
        size_t bo = (size_t)(n0 + row) * Ks + k0 + cu * 8;
        cp16(base + so,         Ah + ao);
        cp16(base + 16384 + so, Al + ao);
        cp16(base + 32768 + so, Bh + bo);
        cp16(base + 49152 + so, Bl + bo);
    }
    CP_COMMIT();
}

__device__ __forceinline__ void ldfrag(
    u32 (&ah)[4][4], u32 (&al)[4][4], u32 (&bh)[4][2], u32 (&bl)[4][2],
    u32 base, u32 koff, int lrow, int wm, int wn)
{
#pragma unroll
    for (int mt = 0; mt < 4; ++mt) {
        u32 so = SW128((u32)((wm + mt * 16 + lrow) * 128 + koff));
        ldm_x4(ah[mt][0], ah[mt][1], ah[mt][2], ah[mt][3], base + so);
        ldm_x4(al[mt][0], al[mt][1], al[mt][2], al[mt][3], base + 16384 + so);
    }
#pragma unroll
    for (int bt = 0; bt < 2; ++bt) {
        u32 so = SW128((u32)((wn + bt * 16 + lrow) * 128 + koff));
        u32 r0, r1, r2, r3;
        ldm_x4(r0, r1, r2, r3, base + 32768 + so);
        bh[bt * 2][0] = r0; bh[bt * 2][1] = r2;
        bh[bt * 2 + 1][0] = r1; bh[bt * 2 + 1][1] = r3;
        ldm_x4(r0, r1, r2, r3, base + 49152 + so);
        bl[bt * 2][0] = r0; bl[bt * 2][1] = r2;
        bl[bt * 2 + 1][0] = r1; bl[bt * 2 + 1][1] = r3;
    }
}

__device__ __forceinline__ void compute_chunk128(
    float (&acc)[4][4][4], u32 base, int lane, int wm, int wn)
{
    const int lrow = lane & 15;
    const u32 klane = (u32)((lane >> 4) * 16);

    u32 ah[2][4][4], al[2][4][4], bh[2][4][2], bl[2][4][2];
    ldfrag(ah[0], al[0], bh[0], bl[0], base, klane, lrow, wm, wn);

#pragma unroll
    for (int ks = 0; ks < 4; ++ks) {
        const int cur = ks & 1;
        if (ks < 3)
            ldfrag(ah[cur ^ 1], al[cur ^ 1], bh[cur ^ 1], bl[cur ^ 1],
                   base, (u32)((ks + 1) * 32) + klane, lrow, wm, wn);
#pragma unroll
        for (int mt = 0; mt < 4; ++mt)
#pragma unroll
            for (int nt = 0; nt < 4; ++nt)
                mma_bf16(acc[mt][nt], ah[cur][mt], bh[cur][nt]);   // hi*hi
#pragma unroll
        for (int mt = 0; mt < 4; ++mt)
#pragma unroll
            for (int nt = 0; nt < 4; ++nt)
                mma_bf16(acc[mt][nt], ah[cur][mt], bl[cur][nt]);   // hi*lo
#pragma unroll
        for (int mt = 0; mt < 4; ++mt)
#pragma unroll
            for (int nt = 0; nt < 4; ++nt)
                mma_bf16(acc[mt][nt], al[cur][mt], bh[cur][nt]);   // lo*hi
    }
}

// single-pair mainloop (Ks = row stride, Kl = accumulated range)
__device__ __forceinline__ void mainloop128(
    float (&acc)[4][4][4],
    const bf16* __restrict__ Ah, const bf16* __restrict__ Al,
    const bf16* __restrict__ Bh, const bf16* __restrict__ Bl,
    int Ks, int Kl, int m0, int n0, u32 smu, int tid, int lane, int wm, int wn)
{
#pragma unroll
    for (int i = 0; i < 4; ++i)
#pragma unroll
        for (int j = 0; j < 4; ++j)
#pragma unroll
            for (int k2 = 0; k2 < 4; ++k2) acc[i][j][k2] = 0.f;

    const int nch = Kl / 64;
    load_stage128(smu,         Ah, Al, Bh, Bl, Ks, m0, n0, 0,  tid);
    load_stage128(smu + 65536, Ah, Al, Bh, Bl, Ks, m0, n0, 64, tid);

    int sl_next = 2, sl_cur = 0;
    for (int c = 0; c < nch; ++c) {
        CP_WAIT(1);
        __syncthreads();
        if (c + 2 < nch)
            load_stage128(smu + sl_next * 65536, Ah, Al, Bh, Bl, Ks, m0, n0, (c + 2) * 64, tid);
        else
            CP_COMMIT();
        compute_chunk128(acc, smu + sl_cur * 65536, lane, wm, wn);
        sl_next = (sl_next == 2) ? 0 : sl_next + 1;
        sl_cur  = (sl_cur  == 2) ? 0 : sl_cur  + 1;
    }
}

// dual-pair mainloop: acc = A0@B0^T + A1@B1^T (pair1 skipped if A1h==nullptr).
__device__ __forceinline__ void mainloop_dual(
    float (&acc)[4][4][4],
    const bf16* __restrict__ A0h, const bf16* __restrict__ A0l,
    const bf16* __restrict__ B0h, const bf16* __restrict__ B0l,
    const bf16* __restrict__ A1h, const bf16* __restrict__ A1l,
    const bf16* __restrict__ B1h, const bf16* __restrict__ B1l,
    int m0, int n0, u32 smu, int tid, int lane, int wm, int wn)
{
#pragma unroll
    for (int i = 0; i < 4; ++i)
#pragma unroll
        for (int j = 0; j < 4; ++j)
#pragma unroll
            for (int k2 = 0; k2 < 4; ++k2) acc[i][j][k2] = 0.f;

    const int n1 = 16;                       // 1024/64
    const int nch = A1h ? 32 : 16;

    auto ld = [&](int c, u32 base) {
        if (c < n1) load_stage128(base, A0h, A0l, B0h, B0l, 1024, m0, n0, c * 64, tid);
        else        load_stage128(base, A1h, A1l, B1h, B1l, 1024, m0, n0, (c - n1) * 64, tid);
    };

    ld(0, smu);
    ld(1, smu + 65536);

    int sl_next = 2, sl_cur = 0;
    for (int c = 0; c < nch; ++c) {
        CP_WAIT(1);
        __syncthreads();
        if (c + 2 < nch)
            ld(c + 2, smu + sl_next * 65536);
        else
            CP_COMMIT();
        compute_chunk128(acc, smu + sl_cur * 65536, lane, wm, wn);
        sl_next = (sl_next == 2) ? 0 : sl_next + 1;
        sl_cur  = (sl_cur  == 2) ? 0 : sl_cur  + 1;
    }
}

// ---- standard epilogue ----
__device__ __forceinline__ void epi_std(
    float (&acc)[4][4][4], int m0, int n0, int lane, int wm, int wn, int N,
    const float* __restrict__ bias, const float* __restrict__ Cadd,
    float* __restrict__ Cf, bf16* __restrict__ Chi, bf16* __restrict__ Clo,
    bool relu)
{
    const int r = lane >> 2, cp = (lane & 3) * 2;
#pragma unroll
    for (int mt = 0; mt < 4; ++mt)
#pragma unroll
        for (int nt = 0; nt < 4; ++nt)
#pragma unroll
            for (int half = 0; half < 2; ++half) {
                const int m = m0 + wm + mt * 16 + r + half * 8;
                const int n = n0 + wn + nt * 8 + cp;
                float v0 = acc[mt][nt][half * 2];
                float v1 = acc[mt][nt][half * 2 + 1];
                if (bias) { v0 += bias[n]; v1 += bias[n + 1]; }
                if (Cadd) { const float* p = Cadd + (size_t)m * N + n;
                            v0 += p[0]; v1 += p[1]; }
                if (relu) { v0 = fmaxf(v0, 0.f); v1 = fmaxf(v1, 0.f); }
                if (Cf) *(float2*)(Cf + (size_t)m * N + n) = make_float2(v0, v1);
                if (Chi) {
                    __nv_bfloat162 hv = __float22bfloat162_rn(make_float2(v0, v1));
                    float2 hf2 = __bfloat1622float2(hv);
                    __nv_bfloat162 lv = __float22bfloat162_rn(
                        make_float2(v0 - hf2.x, v1 - hf2.y));
                    *(__nv_bfloat162*)(Chi + (size_t)m * N + n) = hv;
                    *(__nv_bfloat162*)(Clo + (size_t)m * N + n) = lv;
                }
            }
}

// ---- LSTM-cell epilogue ----
__device__ __forceinline__ void epi_cell(
    float (&acc)[4][4][4], int m0, int n0, int lane, int wm, int wn,
    const float* __restrict__ bias, const float* __restrict__ Cadd,
    float* __restrict__ cbuf, bf16* __restrict__ hh, bf16* __restrict__ hl,
    float* __restrict__ hf, bool zc)
{
    const int r = lane >> 2, cp = (lane & 3) * 2;
#pragma unroll
    for (int mt = 0; mt < 4; ++mt)
#pragma unroll
        for (int nt = 0; nt < 4; ++nt)
#pragma unroll
            for (int half = 0; half < 2; ++half) {
                const int m = m0 + wm + mt * 16 + r + half * 8;
                const int n = n0 + wn + nt * 8 + cp;
                float v0 = acc[mt][nt][half * 2];
                float v1 = acc[mt][nt][half * 2 + 1];
                if (bias) { v0 += bias[n]; v1 += bias[n + 1]; }
                if (Cadd) { const float* p = Cadd + (size_t)m * 4096 + n;
                            v0 += p[0]; v1 += p[1]; }
                float w0 = __shfl_xor_sync(0xFFFFFFFFu, v0, 1);
                float w1 = __shfl_xor_sync(0xFFFFFFFFu, v1, 1);
                if ((lane & 1) == 0) {
                    const int hc = n >> 2;
                    const size_t hidx = (size_t)m * 1024 + hc;
                    float cprev = zc ? 0.f : cbuf[hidx];
                    float cc = sigf(v1) * cprev + sigf(v0) * tanhfa(w0);
                    cbuf[hidx] = cc;
                    float h = sigf(w1) * tanhfa(cc);
                    bf16 hb = __float2bfloat16(h);
                    hh[hidx] = hb;
                    hl[hidx] = __float2bfloat16(h - __bfloat162float(hb));
                    if (hf) hf[hidx] = h;
                }
            }
}

// ================= GEMM kernels =================
// layer-1 split-K=4 GEMM: grid (8, 160). kh = y/40 selects K quarter (3136 each).
__global__ void __launch_bounds__(256, 1) gemm_l1_sk(
    const bf16* __restrict__ xh, const bf16* __restrict__ xl,
    const bf16* __restrict__ qWh, const bf16* __restrict__ qWl,
    const bf16* __restrict__ rxh, const bf16* __restrict__ rxl,
    const bf16* __restrict__ iWh, const bf16* __restrict__ iWl,
    float* __restrict__ p0, float* __restrict__ p1,
    float* __restrict__ p2, float* __restrict__ p3)
{
    extern __shared__ char sm[];
    const int tid = threadIdx.x, wid = tid >> 5, lane = tid & 31;
    const int wm = (wid >> 2) * 64, wn = (wid & 3) * 32;
    const int kh = (int)blockIdx.y / 40;        // 0..3
    const int yy = (int)blockIdx.y - kh * 40;
    const bool r0 = yy < 8;
    const int m0 = (r0 ? yy : yy - 8) * 128;
    const int n0 = blockIdx.x * 128;
    const u32 smu = smem_u32(sm);
    const int kbeg = kh * 3136;

    const bf16* Ah = (r0 ? xh : rxh) + kbeg;
    const bf16* Al = (r0 ? xl : rxl) + kbeg;
    const bf16* Bh = (r0 ? qWh : iWh) + kbeg;
    const bf16* Bl = (r0 ? qWl : iWl) + kbeg;

    float acc[4][4][4];
    mainloop128(acc, Ah, Al, Bh, Bl, 12544, 3136, m0, n0, smu, tid, lane, wm, wn);

    const int mo = (r0 ? 0 : 1024) + m0;
    float* P = (kh == 0) ? p0 : (kh == 1) ? p1 : (kh == 2) ? p2 : p3;
    epi_std(acc, mo, n0, lane, wm, wn, 1024, nullptr, nullptr, P, nullptr, nullptr, false);
}

// combine l1 split-K partials: v = p0+p1+p2+p3 + bias; relu; bf16 hi/lo out.
__global__ void combine_l1_k(
    const float* __restrict__ p0, const float* __restrict__ p1,
    const float* __restrict__ p2, const float* __restrict__ p3,
    const float* __restrict__ qb1, const float* __restrict__ ib1,
    bf16* __restrict__ q1h, bf16* __restrict__ q1l,
    bf16* __restrict__ r1h, bf16* __restrict__ r1l)
{
    size_t i = ((size_t)blockIdx.x * 256 + threadIdx.x) * 8;
    int row = (int)(i >> 10), n = (int)(i & 1023);
    const float* bias; bf16 *oh, *ol; size_t o;
    if (row < 1024) { bias = qb1; oh = q1h; ol = q1l; o = i; }
    else            { bias = ib1; oh = r1h; ol = r1l; o = i - 1024u * 1024u; }
    __nv_bfloat162 hv[4], lv[4];
#pragma unroll
    for (int b = 0; b < 4; ++b) {
        float2 a = *(const float2*)(p0 + i + b * 2);
        float2 c = *(const float2*)(p1 + i + b * 2);
        float2 d = *(const float2*)(p2 + i + b * 2);
        float2 e = *(const float2*)(p3 + i + b * 2);
        float2 bi = *(const float2*)(bias + n + b * 2);
        float2 v;
        v.x = fmaxf((a.x + c.x) + (d.x + e.x) + bi.x, 0.f);
        v.y = fmaxf((a.y + c.y) + (d.y + e.y) + bi.y, 0.f);
        hv[b] = __float22bfloat162_rn(v);
        float2 hf2 = __bfloat1622float2(hv[b]);
        lv[b] = __float22bfloat162_rn(make_float2(v.x - hf2.x, v.y - hf2.y));
    }
    *(uint4*)(oh + o) = *(const uint4*)(hv);
    *(uint4*)(ol + o) = *(const uint4*)(lv);
}

// layer-2 dual-region MLP: region0 (q, nby0 row-blocks) + region1 (i). N=1024.
__global__ void __launch_bounds__(256, 1) mlp_l2(
    const bf16* __restrict__ A0h, const bf16* __restrict__ A0l,
    const bf16* __restrict__ B0h, const bf16* __restrict__ B0l,
    const float* __restrict__ b0, float* __restrict__ C0f,
    bf16* __restrict__ C0h, bf16* __restrict__ C0l, int nby0,
    const bf16* __restrict__ A1h, const bf16* __restrict__ A1l,
    const bf16* __restrict__ B1h, const bf16* __restrict__ B1l,
    const float* __restrict__ b1, float* __restrict__ C1f,
    bf16* __restrict__ C1h, bf16* __restrict__ C1l)
{
    extern __shared__ char sm[];
    const int tid = threadIdx.x, wid = tid >> 5, lane = tid & 31;
    const int wm = (wid >> 2) * 64, wn = (wid & 3) * 32;
    const bool r0 = (int)blockIdx.y < nby0;
    const int m0 = (r0 ? blockIdx.y : blockIdx.y - nby0) * 128;
    const int n0 = blockIdx.x * 128;
    const u32 smu = smem_u32(sm);

    float acc[4][4][4];
    mainloop128(acc, r0 ? A0h : A1h, r0 ? A0l : A1l, r0 ? B0h : B1h, r0 ? B0l : B1l,
                1024, 1024, m0, n0, smu, tid, lane, wm, wn);
    epi_std(acc, m0, n0, lane, wm, wn, 1024,
            r0 ? b0 : b1, nullptr,
            r0 ? C0f : C1f, r0 ? C0h : C1h, r0 ? C0l : C1l, false);
}

// xp = r @ Wih1'^T + bs1  (M=4096, N=4096, K=1024)
__global__ void __launch_bounds__(256, 1) gemm_xp(
    const bf16* __restrict__ Ah, const bf16* __restrict__ Al,
    const bf16* __restrict__ Bh, const bf16* __restrict__ Bl,
    const float* __restrict__ bias, float* __restrict__ Cf)
{
    extern __shared__ char sm[];
    const int tid = threadIdx.x, wid = tid >> 5, lane = tid & 31;
    const int wm = (wid >> 2) * 64, wn = (wid & 3) * 32;
    const int m0 = blockIdx.y * 128, n0 = blockIdx.x * 128;
    const u32 smu = smem_u32(sm);

    float acc[4][4][4];
    mainloop128(acc, Ah, Al, Bh, Bl, 1024, 1024, m0, n0, smu, tid, lane, wm, wn);
    epi_std(acc, m0, n0, lane, wm, wn, 4096, bias, nullptr, Cf, nullptr, nullptr, false);
}

// LSTM combo: grid (32, 8) [or (32,4) for the tail, region2 only].
// LONG-FIRST: y<4 (or all of the tail) = layer2(t-1) dual-pair; y>=4 = layer1(t).
__global__ void __launch_bounds__(256, 1) lstm_combo(
    const bf16* __restrict__ h1rh, const bf16* __restrict__ h1rl,
    const bf16* __restrict__ Whh1h, const bf16* __restrict__ Whh1l,
    const float* __restrict__ xpt, float* __restrict__ c1,
    bf16* __restrict__ h1wh, bf16* __restrict__ h1wl,
    const bf16* __restrict__ Wih2h, const bf16* __restrict__ Wih2l,
    const bf16* __restrict__ h2rh, const bf16* __restrict__ h2rl,
    const bf16* __restrict__ Whh2h, const bf16* __restrict__ Whh2l,
    const float* __restrict__ bs2, float* __restrict__ c2,
    bf16* __restrict__ h2wh, bf16* __restrict__ h2wl,
    float* __restrict__ h2f, int zc)
{
    extern __shared__ char sm[];
    const int tid = threadIdx.x, wid = tid >> 5, lane = tid & 31;
    const int wm = (wid >> 2) * 64, wn = (wid & 3) * 32;
    const bool g2 = (gridDim.y == 4) || ((int)blockIdx.y < 4);
    const int yy = (gridDim.y == 8 && !g2) ? (int)blockIdx.y - 4 : (int)blockIdx.y;
    const int m0 = yy * 128;
    const int n0 = blockIdx.x * 128;
    const u32 smu = smem_u32(sm);

    float acc[4][4][4];
    if (!g2) {
        mainloop_dual(acc, h1rh, h1rl, Whh1h, Whh1l,
                      nullptr, nullptr, nullptr, nullptr,
                      m0, n0, smu, tid, lane, wm, wn);
        epi_cell(acc, m0, n0, lane, wm, wn, nullptr, xpt, c1, h1wh, h1wl, nullptr, false);
    } else {
        mainloop_dual(acc, h1rh, h1rl, Wih2h, Wih2l,
                      h2rh, h2rl, Whh2h, Whh2l,
                      m0, n0, smu, tid, lane, wm, wn);
        epi_cell(acc, m0, n0, lane, wm, wn, bs2, nullptr, c2, h2wh, h2wl, h2f, zc != 0);
    }
}

// ================= elementwise kernels =================
// packed bf16 hi/lo split of 16 consecutive floats
__device__ __forceinline__ void split16(const float* __restrict__ s,
                                        bf16* __restrict__ hi, bf16* __restrict__ lo)
{
    __nv_bfloat162 hv[8], lv[8];
#pragma unroll
    for (int b = 0; b < 8; ++b) {
        float2 v = ((const float2*)s)[b];
        hv[b] = __float22bfloat162_rn(v);
        float2 hf2 = __bfloat1622float2(hv[b]);
        lv[b] = __float22bfloat162_rn(make_float2(v.x - hf2.x, v.y - hf2.y));
    }
    ((uint4*)hi)[0] = ((const uint4*)hv)[0];
    ((uint4*)hi)[1] = ((const uint4*)hv)[1];
    ((uint4*)lo)[0] = ((const uint4*)lv)[0];
    ((uint4*)lo)[1] = ((const uint4*)lv)[1];
}

__global__ void split_all_k(
    const float* __restrict__ s0, bf16* __restrict__ h0, bf16* __restrict__ l0,
    const float* __restrict__ s1, bf16* __restrict__ h1, bf16* __restrict__ l1,
    const float* __restrict__ s2, bf16* __restrict__ h2, bf16* __restrict__ l2,
    const float* __restrict__ s3, bf16* __restrict__ h3, bf16* __restrict__ l3,
    const float* __restrict__ s4, bf16* __restrict__ h4, bf16* __restrict__ l4,
    const float* __restrict__ s5, bf16* __restrict__ h5, bf16* __restrict__ l5)
{
    int b = blockIdx.x;
    const float* s; bf16 *h, *l; int rb;
    if (b < 9408)      { int t = b / 3136; rb = b - t * 3136;
                         s = t == 0 ? s0 : (t == 1 ? s1 : s2);
                         h = t == 0 ? h0 : (t == 1 ? h1 : h2);
                         l = t == 0 ? l0 : (t == 1 ? l1 : l2); }
    else if (b < 9920) { int t = (b - 9408) / 256; rb = (b - 9408) - t * 256;
                         s = t ? s4 : s3; h = t ? h4 : h3; l = t ? l4 : l3; }
    else               { rb = b - 9920; s = s5; h = h5; l = l5; }
    size_t i = ((size_t)rb * 256 + threadIdx.x) * 16;
    split16(s + i, h + i, l + i);
}

// split + gate-permute 4 LSTM weights; block 4096 additionally does biasperm.
__global__ void splitperm4_k(
    const float* __restrict__ W0, bf16* __restrict__ h0, bf16* __restrict__ l0,
    const float* __restrict__ W1, bf16* __restrict__ h1, bf16* __restrict__ l1,
    const float* __restrict__ W2, bf16* __restrict__ h2, bf16* __restrict__ l2,
    const float* __restrict__ W3, bf16* __restrict__ h3, bf16* __restrict__ l3,
    const float* __restrict__ bih1, const float* __restrict__ bhh1,
    const float* __restrict__ bih2, const float* __restrict__ bhh2,
    float* __restrict__ bs1, float* __restrict__ bs2)
{
    if (blockIdx.x == 4096) {   // bias permute: 4096 elems over 256 threads
        int tid = threadIdx.x;
#pragma unroll
        for (int b = 0; b < 16; ++b) {
            int j = tid + b * 256;
            int o = (j >> 2) + ((j & 3) << 10);
            bs1[j] = bih1[o] + bhh1[o];
            bs2[j] = bih2[o] + bhh2[o];
        }
        return;
    }
    int t = blockIdx.x >> 10, rb = blockIdx.x & 1023;
    const float* W = t == 0 ? W0 : (t == 1 ? W1 : (t == 2 ? W2 : W3));
    bf16* hi = t == 0 ? h0 : (t == 1 ? h1 : (t == 2 ? h2 : h3));
    bf16* lo = t == 0 ? l0 : (t == 1 ? l1 : (t == 2 ? l2 : l3));
    size_t gi = ((size_t)rb * 256 + threadIdx.x) * 16;
    int r = (int)(gi >> 10), col = (int)(gi & 1023);
    int ro = ((r & 1023) << 2) | (r >> 10);
    size_t o = (size_t)ro * 1024 + col;
    split16(W + gi, hi + o, lo + o);
}

__global__ void cell1_t0_k(const float* __restrict__ xp0, float* __restrict__ c1,
                           bf16* __restrict__ hh, bf16* __restrict__ hl)
{
    int idx = blockIdx.x * blockDim.x + threadIdx.x;
    int m = idx >> 10, hc = idx & 1023;
    float4 g = *(const float4*)(xp0 + (size_t)m * 4096 + hc * 4);
    float cc = sigf(g.x) * tanhfa(g.z);
    c1[idx] = cc;
    float h = sigf(g.w) * tanhfa(cc);
    bf16 hb = __float2bfloat16(h);
    hh[idx] = hb;
    hl[idx] = __float2bfloat16(h - __bfloat162float(hb));
}

// ================= final einsum =================
__global__ void final_k(const float* __restrict__ q, const float* __restrict__ h,
                        float* __restrict__ out)
{
    __shared__ float qs[32][33];
    __shared__ float hs[64][33];
    const int b  = blockIdx.x >> 2;
    const int rt = blockIdx.x & 3;
    const int tid = threadIdx.x;
    const int r  = tid & 31;
    const int cg = tid >> 5;

    float acc[8] = {0.f, 0.f, 0.f, 0.f, 0.f, 0.f, 0.f, 0.f};
    for (int k0 = 0; k0 < 1024; k0 += 32) {
        __syncthreads();
        for (int i = tid; i < 32 * 32; i += 256) {
            int rr = i >> 5, kk = i & 31;
            qs[rr][kk] = q[(size_t)(b * 128 + rt * 32 + rr) * 1024 + k0 + kk];
        }
        for (int i = tid; i < 64 * 32; i += 256) {
            int rr = i >> 5, kk = i & 31;
            hs[rr][kk] = h[(size_t)(b * 64 + rr) * 1024 + k0 + kk];
        }
        __syncthreads();
#pragma unroll
        for (int kk = 0; kk < 32; ++kk) {
            float qa = qs[r][kk];
#pragma unroll
            for (int j = 0; j < 8; ++j) acc[j] += qa * hs[cg * 8 + j][kk];
        }
    }
    const int row = rt * 32 + r;
    float* op = out + ((size_t)b * 128 + row) * 65;
#pragma unroll
    for (int j = 0; j < 8; ++j) op[1 + cg * 8 + j] = acc[j];
    if (cg == 0) op[0] = 0.f;
}

// ================= host =================
extern "C" void kernel_launch(void* const* d_in, const int* in_sizes, int n_in,
                              void* d_out, int out_size)
{
    const float* x    = (const float*)d_in[0];
    const float* refx = (const float*)d_in[1];
    const float* qW1  = (const float*)d_in[2];
    const float* qb1  = (const float*)d_in[3];
    const float* qW2  = (const float*)d_in[4];
    const float* qb2  = (const float*)d_in[5];
    const float* iW1  = (const float*)d_in[6];
    const float* ib1  = (const float*)d_in[7];
    const float* iW2  = (const float*)d_in[8];
    const float* ib2  = (const float*)d_in[9];
    const float* Wih1 = (const float*)d_in[10];
    const float* Whh1 = (const float*)d_in[11];
    const float* bih1 = (const float*)d_in[12];
    const float* bhh1 = (const float*)d_in[13];
    const float* Wih2 = (const float*)d_in[14];
    const float* Whh2 = (const float*)d_in[15];
    const float* bih2 = (const float*)d_in[16];
    const float* bhh2 = (const float*)d_in[17];
    float* out = (float*)d_out;

    cudaFuncSetAttribute(gemm_l1_sk, cudaFuncAttributeMaxDynamicSharedMemorySize, SMEM_GEMM);
    cudaFuncSetAttribute(mlp_l2,     cudaFuncAttributeMaxDynamicSharedMemorySize, SMEM_GEMM);
    cudaFuncSetAttribute(gemm_xp,    cudaFuncAttributeMaxDynamicSharedMemorySize, SMEM_GEMM);
    cudaFuncSetAttribute(lstm_combo, cudaFuncAttributeMaxDynamicSharedMemorySize, SMEM_GEMM);

#define SYM(v, s) cudaGetSymbolAddress((void**)&v, s)
    bf16 *xh, *xl, *rxh, *rxl, *qW1h, *qW1l, *iW1h, *iW1l, *qW2h, *qW2l, *iW2h, *iW2l;
    bf16 *Wih1h, *Wih1l, *Whh1h, *Whh1l, *Wih2h, *Wih2l, *Whh2h, *Whh2l;
    bf16 *q1h, *q1l, *r1h, *r1l, *rh, *rl, *h1hb, *h1lb, *h2hb, *h2lb;
    float *bs1, *bs2, *q, *xp, *c1, *c2, *h2f, *p0, *p1, *p2, *p3;
    SYM(xh, g_x_h);   SYM(xl, g_x_l);   SYM(rxh, g_rx_h);   SYM(rxl, g_rx_l);
    SYM(qW1h, g_qW1_h); SYM(qW1l, g_qW1_l); SYM(iW1h, g_iW1_h); SYM(iW1l, g_iW1_l);
    SYM(qW2h, g_qW2_h); SYM(qW2l, g_qW2_l); SYM(iW2h, g_iW2_h); SYM(iW2l, g_iW2_l);
    SYM(Wih1h, g_Wih1_h); SYM(Wih1l, g_Wih1_l); SYM(Whh1h, g_Whh1_h); SYM(Whh1l, g_Whh1_l);
    SYM(Wih2h, g_Wih2_h); SYM(Wih2l, g_Wih2_l); SYM(Whh2h, g_Whh2_h); SYM(Whh2l, g_Whh2_l);
    SYM(q1h, g_q1_h); SYM(q1l, g_q1_l); SYM(r1h, g_r1_h); SYM(r1l, g_r1_l);
    SYM(rh, g_r_h);   SYM(rl, g_r_l);
    SYM(h1hb, g_h1_h); SYM(h1lb, g_h1_l); SYM(h2hb, g_h2_h); SYM(h2lb, g_h2_l);
    SYM(bs1, g_bs1); SYM(bs2, g_bs2);
    SYM(q, g_q); SYM(xp, g_xp);
    SYM(c1, g_c1); SYM(c2, g_c2); SYM(h2f, g_h2f);
    SYM(p0, g_p0); SYM(p1, g_p1); SYM(p2, g_p2); SYM(p3, g_p3);
#undef SYM
    const size_t HB = 512u * 1024;
    bf16* h1h[2] = {h1hb, h1hb + HB};
    bf16* h1l[2] = {h1lb, h1lb + HB};
    bf16* h2h[2] = {h2hb, h2hb + HB};
    bf16* h2l[2] = {h2lb, h2lb + HB};

    // ---- splits (biasperm merged into splitperm4 as block 4096) ----
    split_all_k<<<22464, 256>>>(x, xh, xl, qW1, qW1h, qW1l, iW1, iW1h, iW1l,
                                qW2, qW2h, qW2l, iW2, iW2h, iW2l, refx, rxh, rxl);
    splitperm4_k<<<4097, 256>>>(Wih1, Wih1h, Wih1l, Whh1, Whh1h, Whh1l,
                                Wih2, Wih2h, Wih2l, Whh2, Whh2h, Whh2l,
                                bih1, bhh1, bih2, bhh2, bs1, bs2);

    // ---- layer 1: split-K=4 GEMM + combine ----
    gemm_l1_sk<<<dim3(8, 160), 256, SMEM_GEMM>>>(
        xh, xl, qW1h, qW1l, rxh, rxl, iW1h, iW1l, p0, p1, p2, p3);
    combine_l1_k<<<2560, 256>>>(p0, p1, p2, p3, qb1, ib1, q1h, q1l, r1h, r1l);

    // ---- layer 2 (dual region, single pass) ----
    mlp_l2<<<dim3(8, 40), 256, SMEM_GEMM>>>(
        q1h, q1l, qW2h, qW2l, qb2, q, nullptr, nullptr, 8,
        r1h, r1l, iW2h, iW2l, ib2, nullptr, rh, rl);

    // ---- xp = r @ Wih1'^T + bs1 ----
    gemm_xp<<<dim3(32, 32), 256, SMEM_GEMM>>>(rh, rl, Wih1h, Wih1l, bs1, xp);

    // ---- LSTM: t=0 layer1 from xp, then 7 combo launches + layer2(7) tail ----
    cell1_t0_k<<<2048, 256>>>(xp, c1, h1h[0], h1l[0]);

    for (int t = 1; t <= 7; ++t) {
        const int pr = (t - 1) & 1, pw = t & 1;
        const int h2r = t & 1, h2w = (t - 1) & 1;
        lstm_combo<<<dim3(32, 8), 256, SMEM_GEMM>>>(
            h1h[pr], h1l[pr],
            Whh1h, Whh1l, xp + (size_t)t * 512 * 4096, c1, h1h[pw], h1l[pw],
            Wih2h, Wih2l,
            (t == 1) ? nullptr : h2h[h2r], (t == 1) ? nullptr : h2l[h2r],
            Whh2h, Whh2l, bs2, c2, h2h[h2w], h2l[h2w], h2f, (t == 1) ? 1 : 0);
    }
    // tail: layer2(7) — reads h1(7) (parity 1) and h2(6) (parity 0), writes h2(7)
    lstm_combo<<<dim3(32, 4), 256, SMEM_GEMM>>>(
        h1h[1], h1l[1],
        Whh1h, Whh1l, nullptr, c1, nullptr, nullptr,
        Wih2h, Wih2l, h2h[0], h2l[0],
        Whh2h, Whh2l, bs2, c2, h2h[1], h2l[1], h2f, 0);

    // ---- out ----
    final_k<<<32, 256>>>(q, h2f, out);
}

// round 17
// speedup vs baseline: 1.0099x; 1.0099x over previous
#include <cuda_runtime.h>
#include <cuda_bf16.h>

typedef unsigned long long u64;
typedef unsigned int u32;
typedef __nv_bfloat16 bf16;

// ================= scratch (device globals; no allocation) =================
__device__ bf16 g_x_h [1024u*12544], g_x_l [1024u*12544];
__device__ bf16 g_rx_h[4096u*12544], g_rx_l[4096u*12544];
__device__ bf16 g_qW1_h[1024u*12544], g_qW1_l[1024u*12544];
__device__ bf16 g_iW1_h[1024u*12544], g_iW1_l[1024u*12544];
__device__ bf16 g_qW2_h[1024u*1024], g_qW2_l[1024u*1024];
__device__ bf16 g_iW2_h[1024u*1024], g_iW2_l[1024u*1024];
// permuted (gate-interleaved) LSTM weights
__device__ bf16 g_Wih1_h[4096u*1024], g_Wih1_l[4096u*1024];
__device__ bf16 g_Whh1_h[4096u*1024], g_Whh1_l[4096u*1024];
__device__ bf16 g_Wih2_h[4096u*1024], g_Wih2_l[4096u*1024];
__device__ bf16 g_Whh2_h[4096u*1024], g_Whh2_l[4096u*1024];
__device__ float g_bs1[4096], g_bs2[4096];
// split-K partials for layer 1 (combined 5120 rows: q 0..1023, i 1024..5119)
__device__ float g_p0[5120u*1024], g_p1[5120u*1024];
__device__ float g_p2[5120u*1024], g_p3[5120u*1024];
__device__ bf16 g_q1_h[1024u*1024], g_q1_l[1024u*1024];
__device__ bf16 g_r1_h[4096u*1024], g_r1_l[4096u*1024];
__device__ bf16 g_r_h [4096u*1024], g_r_l [4096u*1024];
__device__ bf16 g_h1_h[2][512u*1024], g_h1_l[2][512u*1024];   // double-buffered
__device__ bf16 g_h2_h[2][512u*1024], g_h2_l[2][512u*1024];   // double-buffered
__device__ float g_q  [1024u*1024];
__device__ float g_xp [4096ull*4096];
__device__ float g_c1[512u*1024], g_c2[512u*1024], g_h2f[512u*1024];

// ================= PTX helpers (baseline sm_80+ PTX only) =================
__device__ __forceinline__ u32 smem_u32(const void* p) {
    u32 a;
    asm("{ .reg .u64 t; cvta.to.shared.u64 t, %1; cvt.u32.u64 %0, t; }" : "=r"(a) : "l"(p));
    return a;
}
#define SW128(o) ((o) ^ (((o) >> 3) & 0x70))

__device__ __forceinline__ void cp16(u32 dst, const void* src) {
    asm volatile("cp.async.cg.shared.global [%0], [%1], 16;" :: "r"(dst), "l"(src));
}
#define CP_COMMIT()  asm volatile("cp.async.commit_group;" ::: "memory")
#define CP_WAIT(n)   asm volatile("cp.async.wait_group %0;" :: "n"(n) : "memory")

__device__ __forceinline__ void ldm_x4(u32& r0, u32& r1, u32& r2, u32& r3, u32 addr) {
    asm volatile("ldmatrix.sync.aligned.m8n8.x4.shared.b16 {%0,%1,%2,%3}, [%4];"
                 : "=r"(r0), "=r"(r1), "=r"(r2), "=r"(r3) : "r"(addr));
}
__device__ __forceinline__ void mma_bf16(float* d, const u32* a, const u32* b) {
    asm volatile("mma.sync.aligned.m16n8k16.row.col.f32.bf16.bf16.f32 "
                 "{%0,%1,%2,%3}, {%4,%5,%6,%7}, {%8,%9}, {%0,%1,%2,%3};"
                 : "+f"(d[0]), "+f"(d[1]), "+f"(d[2]), "+f"(d[3])
                 : "r"(a[0]), "r"(a[1]), "r"(a[2]), "r"(a[3]), "r"(b[0]), "r"(b[1]));
}

__device__ __forceinline__ float sigf(float x) {
    return __fdividef(1.0f, 1.0f + __expf(-x));
}
__device__ __forceinline__ float tanhfa(float x) {
    return __fdividef(2.0f, 1.0f + __expf(-2.0f * x)) - 1.0f;
}

static const int SMEM_GEMM = 196608;   // 3 x 64KB stages

// ================= GEMM machinery (R14 config, unchanged) =================
__device__ __forceinline__ void load_stage128(
    u32 base,
    const bf16* __restrict__ Ah, const bf16* __restrict__ Al,
    const bf16* __restrict__ Bh, const bf16* __restrict__ Bl,
    int Ks, int m0, int n0, int k0, int tid)
{
#pragma unroll
    for (int i = 0; i < 4; ++i) {
        int u = tid + i * 256;
        int row = u >> 3, cu = u & 7;
        u32 so = SW128((u32)(row * 128 + cu * 16));
        size_t ao = (size_t)(m0 + row) * Ks + k0 + cu * 8;
        size_t bo = (size_t)(n0 + row) * Ks + k0 + cu * 8;
        cp16(base + so,         Ah + ao);
        cp16(base + 16384 + so, Al + ao);
        cp16(base + 32768 + so, Bh + bo);
        cp16(base + 49152 + so, Bl + bo);
    }
    CP_COMMIT();
}

__device__ __forceinline__ void ldfrag(
    u32 (&ah)[4][4], u32 (&al)[4][4], u32 (&bh)[4][2], u32 (&bl)[4][2],
    u32 base, u32 koff, int lrow, int wm, int wn)
{
#pragma unroll
    for (int mt = 0; mt < 4; ++mt) {
        u32 so = SW128((u32)((wm + mt * 16 + lrow) * 128 + koff));
        ldm_x4(ah[mt][0], ah[mt][1], ah[mt][2], ah[mt][3], base + so);
        ldm_x4(al[mt][0], al[mt][1], al[mt][2], al[mt][3], base + 16384 + so);
    }
#pragma unroll
    for (int bt = 0; bt < 2; ++bt) {
        u32 so = SW128((u32)((wn + bt * 16 + lrow) * 128 + koff));
        u32 r0, r1, r2, r3;
        ldm_x4(r0, r1, r2, r3, base + 32768 + so);
        bh[bt * 2][0] = r0; bh[bt * 2][1] = r2;
        bh[bt * 2 + 1][0] = r1; bh[bt * 2 + 1][1] = r3;
        ldm_x4(r0, r1, r2, r3, base + 49152 + so);
        bl[bt * 2][0] = r0; bl[bt * 2][1] = r2;
        bl[bt * 2 + 1][0] = r1; bl[bt * 2 + 1][1] = r3;
    }
}

__device__ __forceinline__ void compute_chunk128(
    float (&acc)[4][4][4], u32 base, int lane, int wm, int wn)
{
    const int lrow = lane & 15;
    const u32 klane = (u32)((lane >> 4) * 16);

    u32 ah[2][4][4], al[2][4][4], bh[2][4][2], bl[2][4][2];
    ldfrag(ah[0], al[0], bh[0], bl[0], base, klane, lrow, wm, wn);

#pragma unroll
    for (int ks = 0; ks < 4; ++ks) {
        const int cur = ks & 1;
        if (ks < 3)
            ldfrag(ah[cur ^ 1], al[cur ^ 1], bh[cur ^ 1], bl[cur ^ 1],
                   base, (u32)((ks + 1) * 32) + klane, lrow, wm, wn);
#pragma unroll
        for (int mt = 0; mt < 4; ++mt)
#pragma unroll
            for (int nt = 0; nt < 4; ++nt)
                mma_bf16(acc[mt][nt], ah[cur][mt], bh[cur][nt]);   // hi*hi
#pragma unroll
        for (int mt = 0; mt < 4; ++mt)
#pragma unroll
            for (int nt = 0; nt < 4; ++nt)
                mma_bf16(acc[mt][nt], ah[cur][mt], bl[cur][nt]);   // hi*lo
#pragma unroll
        for (int mt = 0; mt < 4; ++mt)
#pragma unroll
            for (int nt = 0; nt < 4; ++nt)
                mma_bf16(acc[mt][nt], al[cur][mt], bh[cur][nt]);   // lo*hi
    }
}

// single-pair mainloop (Ks = row stride, Kl = accumulated range)
__device__ __forceinline__ void mainloop128(
    float (&acc)[4][4][4],
    const bf16* __restrict__ Ah, const bf16* __restrict__ Al,
    const bf16* __restrict__ Bh, const bf16* __restrict__ Bl,
    int Ks, int Kl, int m0, int n0, u32 smu, int tid, int lane, int wm, int wn)
{
#pragma unroll
    for (int i = 0; i < 4; ++i)
#pragma unroll
        for (int j = 0; j < 4; ++j)
#pragma unroll
            for (int k2 = 0; k2 < 4; ++k2) acc[i][j][k2] = 0.f;

    const int nch = Kl / 64;
    load_stage128(smu,         Ah, Al, Bh, Bl, Ks, m0, n0, 0,  tid);
    load_stage128(smu + 65536, Ah, Al, Bh, Bl, Ks, m0, n0, 64, tid);

    int sl_next = 2, sl_cur = 0;
    for (int c = 0; c < nch; ++c) {
        CP_WAIT(1);
        __syncthreads();
        if (c + 2 < nch)
            load_stage128(smu + sl_next * 65536, Ah, Al, Bh, Bl, Ks, m0, n0, (c + 2) * 64, tid);
        else
            CP_COMMIT();
        compute_chunk128(acc, smu + sl_cur * 65536, lane, wm, wn);
        sl_next = (sl_next == 2) ? 0 : sl_next + 1;
        sl_cur  = (sl_cur  == 2) ? 0 : sl_cur  + 1;
    }
}

// dual-pair mainloop: acc = A0@B0^T + A1@B1^T (pair1 skipped if A1h==nullptr).
__device__ __forceinline__ void mainloop_dual(
    float (&acc)[4][4][4],
    const bf16* __restrict__ A0h, const bf16* __restrict__ A0l,
    const bf16* __restrict__ B0h, const bf16* __restrict__ B0l,
    const bf16* __restrict__ A1h, const bf16* __restrict__ A1l,
    const bf16* __restrict__ B1h, const bf16* __restrict__ B1l,
    int m0, int n0, u32 smu, int tid, int lane, int wm, int wn)
{
#pragma unroll
    for (int i = 0; i < 4; ++i)
#pragma unroll
        for (int j = 0; j < 4; ++j)
#pragma unroll
            for (int k2 = 0; k2 < 4; ++k2) acc[i][j][k2] = 0.f;

    const int n1 = 16;                       // 1024/64
    const int nch = A1h ? 32 : 16;

    auto ld = [&](int c, u32 base) {
        if (c < n1) load_stage128(base, A0h, A0l, B0h, B0l, 1024, m0, n0, c * 64, tid);
        else        load_stage128(base, A1h, A1l, B1h, B1l, 1024, m0, n0, (c - n1) * 64, tid);
    };

    ld(0, smu);
    ld(1, smu + 65536);

    int sl_next = 2, sl_cur = 0;
    for (int c = 0; c < nch; ++c) {
        CP_WAIT(1);
        __syncthreads();
        if (c + 2 < nch)
            ld(c + 2, smu + sl_next * 65536);
        else
            CP_COMMIT();
        compute_chunk128(acc, smu + sl_cur * 65536, lane, wm, wn);
        sl_next = (sl_next == 2) ? 0 : sl_next + 1;
        sl_cur  = (sl_cur  == 2) ? 0 : sl_cur  + 1;
    }
}

// ---- standard epilogue (R14 scalar form) ----
__device__ __forceinline__ void epi_std(
    float (&acc)[4][4][4], int m0, int n0, int lane, int wm, int wn, int N,
    const float* __restrict__ bias, const float* __restrict__ Cadd,
    float* __restrict__ Cf, bf16* __restrict__ Chi, bf16* __restrict__ Clo,
    bool relu)
{
    const int r = lane >> 2, cp = (lane & 3) * 2;
#pragma unroll
    for (int mt = 0; mt < 4; ++mt)
#pragma unroll
        for (int nt = 0; nt < 4; ++nt)
#pragma unroll
            for (int half = 0; half < 2; ++half) {
                const int m = m0 + wm + mt * 16 + r + half * 8;
                const int n = n0 + wn + nt * 8 + cp;
                float v0 = acc[mt][nt][half * 2];
                float v1 = acc[mt][nt][half * 2 + 1];
                if (bias) { v0 += bias[n]; v1 += bias[n + 1]; }
                if (Cadd) { const float* p = Cadd + (size_t)m * N + n;
                            v0 += p[0]; v1 += p[1]; }
                if (relu) { v0 = fmaxf(v0, 0.f); v1 = fmaxf(v1, 0.f); }
                if (Cf) *(float2*)(Cf + (size_t)m * N + n) = make_float2(v0, v1);
                if (Chi) {
                    bf16 h0 = __float2bfloat16(v0), h1 = __float2bfloat16(v1);
                    bf16 l0 = __float2bfloat16(v0 - __bfloat162float(h0));
                    bf16 l1 = __float2bfloat16(v1 - __bfloat162float(h1));
                    *(__nv_bfloat162*)(Chi + (size_t)m * N + n) = __nv_bfloat162(h0, h1);
                    *(__nv_bfloat162*)(Clo + (size_t)m * N + n) = __nv_bfloat162(l0, l1);
                }
            }
}

// ---- LSTM-cell epilogue ----
__device__ __forceinline__ void epi_cell(
    float (&acc)[4][4][4], int m0, int n0, int lane, int wm, int wn,
    const float* __restrict__ bias, const float* __restrict__ Cadd,
    float* __restrict__ cbuf, bf16* __restrict__ hh, bf16* __restrict__ hl,
    float* __restrict__ hf, bool zc)
{
    const int r = lane >> 2, cp = (lane & 3) * 2;
#pragma unroll
    for (int mt = 0; mt < 4; ++mt)
#pragma unroll
        for (int nt = 0; nt < 4; ++nt)
#pragma unroll
            for (int half = 0; half < 2; ++half) {
                const int m = m0 + wm + mt * 16 + r + half * 8;
                const int n = n0 + wn + nt * 8 + cp;
                float v0 = acc[mt][nt][half * 2];
                float v1 = acc[mt][nt][half * 2 + 1];
                if (bias) { v0 += bias[n]; v1 += bias[n + 1]; }
                if (Cadd) { const float* p = Cadd + (size_t)m * 4096 + n;
                            v0 += p[0]; v1 += p[1]; }
                float w0 = __shfl_xor_sync(0xFFFFFFFFu, v0, 1);
                float w1 = __shfl_xor_sync(0xFFFFFFFFu, v1, 1);
                if ((lane & 1) == 0) {
                    const int hc = n >> 2;
                    const size_t hidx = (size_t)m * 1024 + hc;
                    float cprev = zc ? 0.f : cbuf[hidx];
                    float cc = sigf(v1) * cprev + sigf(v0) * tanhfa(w0);
                    cbuf[hidx] = cc;
                    float h = sigf(w1) * tanhfa(cc);
                    bf16 hb = __float2bfloat16(h);
                    hh[hidx] = hb;
                    hl[hidx] = __float2bfloat16(h - __bfloat162float(hb));
                    if (hf) hf[hidx] = h;
                }
            }
}

// ================= GEMM kernels =================
// layer-1 split-K=4 GEMM: grid (8, 160). kh = y/40 selects K quarter (3136 each).
__global__ void __launch_bounds__(256, 1) gemm_l1_sk(
    const bf16* __restrict__ xh, const bf16* __restrict__ xl,
    const bf16* __restrict__ qWh, const bf16* __restrict__ qWl,
    const bf16* __restrict__ rxh, const bf16* __restrict__ rxl,
    const bf16* __restrict__ iWh, const bf16* __restrict__ iWl,
    float* __restrict__ p0, float* __restrict__ p1,
    float* __restrict__ p2, float* __restrict__ p3)
{
    extern __shared__ char sm[];
    const int tid = threadIdx.x, wid = tid >> 5, lane = tid & 31;
    const int wm = (wid >> 2) * 64, wn = (wid & 3) * 32;
    const int kh = (int)blockIdx.y / 40;        // 0..3
    const int yy = (int)blockIdx.y - kh * 40;
    const bool r0 = yy < 8;
    const int m0 = (r0 ? yy : yy - 8) * 128;
    const int n0 = blockIdx.x * 128;
    const u32 smu = smem_u32(sm);
    const int kbeg = kh * 3136;

    const bf16* Ah = (r0 ? xh : rxh) + kbeg;
    const bf16* Al = (r0 ? xl : rxl) + kbeg;
    const bf16* Bh = (r0 ? qWh : iWh) + kbeg;
    const bf16* Bl = (r0 ? qWl : iWl) + kbeg;

    float acc[4][4][4];
    mainloop128(acc, Ah, Al, Bh, Bl, 12544, 3136, m0, n0, smu, tid, lane, wm, wn);

    const int mo = (r0 ? 0 : 1024) + m0;
    float* P = (kh == 0) ? p0 : (kh == 1) ? p1 : (kh == 2) ? p2 : p3;
    epi_std(acc, mo, n0, lane, wm, wn, 1024, nullptr, nullptr, P, nullptr, nullptr, false);
}

// combine l1 split-K partials (R14 scalar form): v = p0+p1+p2+p3 + bias; relu; bf16 out.
__global__ void combine_l1_k(
    const float* __restrict__ p0, const float* __restrict__ p1,
    const float* __restrict__ p2, const float* __restrict__ p3,
    const float* __restrict__ qb1, const float* __restrict__ ib1,
    bf16* __restrict__ q1h, bf16* __restrict__ q1l,
    bf16* __restrict__ r1h, bf16* __restrict__ r1l)
{
    size_t i = ((size_t)blockIdx.x * 256 + threadIdx.x) * 8;
    int row = (int)(i >> 10), n = (int)(i & 1023);
    const float* bias; bf16 *oh, *ol; size_t o;
    if (row < 1024) { bias = qb1; oh = q1h; ol = q1l; o = i; }
    else            { bias = ib1; oh = r1h; ol = r1l; o = i - 1024u * 1024u; }
    unsigned short hh[8], ll[8];
#pragma unroll
    for (int b = 0; b < 2; ++b) {
        float4 a = *(const float4*)(p0 + i + b * 4);
        float4 c = *(const float4*)(p1 + i + b * 4);
        float4 d = *(const float4*)(p2 + i + b * 4);
        float4 e = *(const float4*)(p3 + i + b * 4);
        float vv[4] = {(a.x + c.x) + (d.x + e.x), (a.y + c.y) + (d.y + e.y),
                       (a.z + c.z) + (d.z + e.z), (a.w + c.w) + (d.w + e.w)};
#pragma unroll
        for (int j = 0; j < 4; ++j) {
            float v = fmaxf(vv[j] + bias[n + b * 4 + j], 0.f);
            bf16 h = __float2bfloat16(v);
            hh[b * 4 + j] = __bfloat16_as_ushort(h);
            ll[b * 4 + j] = __bfloat16_as_ushort(
                __float2bfloat16(v - __bfloat162float(h)));
        }
    }
    *(ushort4*)(oh + o)     = *(const ushort4*)(hh);
    *(ushort4*)(oh + o + 4) = *(const ushort4*)(hh + 4);
    *(ushort4*)(ol + o)     = *(const ushort4*)(ll);
    *(ushort4*)(ol + o + 4) = *(const ushort4*)(ll + 4);
}

// layer-2 dual-region MLP: region0 (q, nby0 row-blocks) + region1 (i). N=1024.
__global__ void __launch_bounds__(256, 1) mlp_l2(
    const bf16* __restrict__ A0h, const bf16* __restrict__ A0l,
    const bf16* __restrict__ B0h, const bf16* __restrict__ B0l,
    const float* __restrict__ b0, float* __restrict__ C0f,
    bf16* __restrict__ C0h, bf16* __restrict__ C0l, int nby0,
    const bf16* __restrict__ A1h, const bf16* __restrict__ A1l,
    const bf16* __restrict__ B1h, const bf16* __restrict__ B1l,
    const float* __restrict__ b1, float* __restrict__ C1f,
    bf16* __restrict__ C1h, bf16* __restrict__ C1l)
{
    extern __shared__ char sm[];
    const int tid = threadIdx.x, wid = tid >> 5, lane = tid & 31;
    const int wm = (wid >> 2) * 64, wn = (wid & 3) * 32;
    const bool r0 = (int)blockIdx.y < nby0;
    const int m0 = (r0 ? blockIdx.y : blockIdx.y - nby0) * 128;
    const int n0 = blockIdx.x * 128;
    const u32 smu = smem_u32(sm);

    float acc[4][4][4];
    mainloop128(acc, r0 ? A0h : A1h, r0 ? A0l : A1l, r0 ? B0h : B1h, r0 ? B0l : B1l,
                1024, 1024, m0, n0, smu, tid, lane, wm, wn);
    epi_std(acc, m0, n0, lane, wm, wn, 1024,
            r0 ? b0 : b1, nullptr,
            r0 ? C0f : C1f, r0 ? C0h : C1h, r0 ? C0l : C1l, false);
}

// xp = r @ Wih1'^T + bs1  (M=4096, N=4096, K=1024)
// Rows 0..511 (t=0) are consumed ONLY by the t=0 layer-1 cell -> fuse it here:
// for m0<512 run epi_cell (zc) writing h1[0]/c1 instead of storing xp.
__global__ void __launch_bounds__(256, 1) gemm_xp(
    const bf16* __restrict__ Ah, const bf16* __restrict__ Al,
    const bf16* __restrict__ Bh, const bf16* __restrict__ Bl,
    const float* __restrict__ bias, float* __restrict__ Cf,
    float* __restrict__ c1, bf16* __restrict__ h1h0, bf16* __restrict__ h1l0)
{
    extern __shared__ char sm[];
    const int tid = threadIdx.x, wid = tid >> 5, lane = tid & 31;
    const int wm = (wid >> 2) * 64, wn = (wid & 3) * 32;
    const int m0 = blockIdx.y * 128, n0 = blockIdx.x * 128;
    const u32 smu = smem_u32(sm);

    float acc[4][4][4];
    mainloop128(acc, Ah, Al, Bh, Bl, 1024, 1024, m0, n0, smu, tid, lane, wm, wn);
    if (m0 < 512)
        epi_cell(acc, m0, n0, lane, wm, wn, bias, nullptr, c1, h1h0, h1l0, nullptr, true);
    else
        epi_std(acc, m0, n0, lane, wm, wn, 4096, bias, nullptr, Cf, nullptr, nullptr, false);
}

// LSTM combo: grid (32, 8) [or (32,4) for the tail, region2 only].
// LONG-FIRST: y<4 (or all of the tail) = layer2(t-1) dual-pair; y>=4 = layer1(t).
__global__ void __launch_bounds__(256, 1) lstm_combo(
    const bf16* __restrict__ h1rh, const bf16* __restrict__ h1rl,
    const bf16* __restrict__ Whh1h, const bf16* __restrict__ Whh1l,
    const float* __restrict__ xpt, float* __restrict__ c1,
    bf16* __restrict__ h1wh, bf16* __restrict__ h1wl,
    const bf16* __restrict__ Wih2h, const bf16* __restrict__ Wih2l,
    const bf16* __restrict__ h2rh, const bf16* __restrict__ h2rl,
    const bf16* __restrict__ Whh2h, const bf16* __restrict__ Whh2l,
    const float* __restrict__ bs2, float* __restrict__ c2,
    bf16* __restrict__ h2wh, bf16* __restrict__ h2wl,
    float* __restrict__ h2f, int zc)
{
    extern __shared__ char sm[];
    const int tid = threadIdx.x, wid = tid >> 5, lane = tid & 31;
    const int wm = (wid >> 2) * 64, wn = (wid & 3) * 32;
    const bool g2 = (gridDim.y == 4) || ((int)blockIdx.y < 4);
    const int yy = (gridDim.y == 8 && !g2) ? (int)blockIdx.y - 4 : (int)blockIdx.y;
    const int m0 = yy * 128;
    const int n0 = blockIdx.x * 128;
    const u32 smu = smem_u32(sm);

    float acc[4][4][4];
    if (!g2) {
        mainloop_dual(acc, h1rh, h1rl, Whh1h, Whh1l,
                      nullptr, nullptr, nullptr, nullptr,
                      m0, n0, smu, tid, lane, wm, wn);
        epi_cell(acc, m0, n0, lane, wm, wn, nullptr, xpt, c1, h1wh, h1wl, nullptr, false);
    } else {
        mainloop_dual(acc, h1rh, h1rl, Wih2h, Wih2l,
                      h2rh, h2rl, Whh2h, Whh2l,
                      m0, n0, smu, tid, lane, wm, wn);
        epi_cell(acc, m0, n0, lane, wm, wn, bs2, nullptr, c2, h2wh, h2wl, h2f, zc != 0);
    }
}

// ================= elementwise kernels =================
// bf16 hi/lo split of 16 consecutive floats (R14 scalar form)
__device__ __forceinline__ void split16(const float* __restrict__ s,
                                        bf16* __restrict__ hi, bf16* __restrict__ lo)
{
    unsigned short hh[16], ll[16];
#pragma unroll
    for (int b = 0; b < 4; ++b) {
        float4 v = ((const float4*)s)[b];
        float vv[4] = {v.x, v.y, v.z, v.w};
#pragma unroll
        for (int j = 0; j < 4; ++j) {
            bf16 h = __float2bfloat16(vv[j]);
            hh[b * 4 + j] = __bfloat16_as_ushort(h);
            ll[b * 4 + j] = __bfloat16_as_ushort(
                __float2bfloat16(vv[j] - __bfloat162float(h)));
        }
    }
    ((uint4*)hi)[0] = *(const uint4*)(hh);
    ((uint4*)hi)[1] = *(const uint4*)(hh + 8);
    ((uint4*)lo)[0] = *(const uint4*)(ll);
    ((uint4*)lo)[1] = *(const uint4*)(ll + 8);
}

__global__ void split_all_k(
    const float* __restrict__ s0, bf16* __restrict__ h0, bf16* __restrict__ l0,
    const float* __restrict__ s1, bf16* __restrict__ h1, bf16* __restrict__ l1,
    const float* __restrict__ s2, bf16* __restrict__ h2, bf16* __restrict__ l2,
    const float* __restrict__ s3, bf16* __restrict__ h3, bf16* __restrict__ l3,
    const float* __restrict__ s4, bf16* __restrict__ h4, bf16* __restrict__ l4,
    const float* __restrict__ s5, bf16* __restrict__ h5, bf16* __restrict__ l5)
{
    int b = blockIdx.x;
    const float* s; bf16 *h, *l; int rb;
    if (b < 9408)      { int t = b / 3136; rb = b - t * 3136;
                         s = t == 0 ? s0 : (t == 1 ? s1 : s2);
                         h = t == 0 ? h0 : (t == 1 ? h1 : h2);
                         l = t == 0 ? l0 : (t == 1 ? l1 : l2); }
    else if (b < 9920) { int t = (b - 9408) / 256; rb = (b - 9408) - t * 256;
                         s = t ? s4 : s3; h = t ? h4 : h3; l = t ? l4 : l3; }
    else               { rb = b - 9920; s = s5; h = h5; l = l5; }
    size_t i = ((size_t)rb * 256 + threadIdx.x) * 16;
    split16(s + i, h + i, l + i);
}

// split + gate-permute 4 LSTM weights; block 4096 additionally does biasperm.
__global__ void splitperm4_k(
    const float* __restrict__ W0, bf16* __restrict__ h0, bf16* __restrict__ l0,
    const float* __restrict__ W1, bf16* __restrict__ h1, bf16* __restrict__ l1,
    const float* __restrict__ W2, bf16* __restrict__ h2, bf16* __restrict__ l2,
    const float* __restrict__ W3, bf16* __restrict__ h3, bf16* __restrict__ l3,
    const float* __restrict__ bih1, const float* __restrict__ bhh1,
    const float* __restrict__ bih2, const float* __restrict__ bhh2,
    float* __restrict__ bs1, float* __restrict__ bs2)
{
    if (blockIdx.x == 4096) {   // bias permute: 4096 elems over 256 threads
        int tid = threadIdx.x;
#pragma unroll
        for (int b = 0; b < 16; ++b) {
            int j = tid + b * 256;
            int o = (j >> 2) + ((j & 3) << 10);
            bs1[j] = bih1[o] + bhh1[o];
            bs2[j] = bih2[o] + bhh2[o];
        }
        return;
    }
    int t = blockIdx.x >> 10, rb = blockIdx.x & 1023;
    const float* W = t == 0 ? W0 : (t == 1 ? W1 : (t == 2 ? W2 : W3));
    bf16* hi = t == 0 ? h0 : (t == 1 ? h1 : (t == 2 ? h2 : h3));
    bf16* lo = t == 0 ? l0 : (t == 1 ? l1 : (t == 2 ? l2 : l3));
    size_t gi = ((size_t)rb * 256 + threadIdx.x) * 16;
    int r = (int)(gi >> 10), col = (int)(gi & 1023);
    int ro = ((r & 1023) << 2) | (r >> 10);
    size_t o = (size_t)ro * 1024 + col;
    split16(W + gi, hi + o, lo + o);
}

// ================= final einsum =================
__global__ void final_k(const float* __restrict__ q, const float* __restrict__ h,
                        float* __restrict__ out)
{
    __shared__ float qs[32][33];
    __shared__ float hs[64][33];
    const int b  = blockIdx.x >> 2;
    const int rt = blockIdx.x & 3;
    const int tid = threadIdx.x;
    const int r  = tid & 31;
    const int cg = tid >> 5;

    float acc[8] = {0.f, 0.f, 0.f, 0.f, 0.f, 0.f, 0.f, 0.f};
    for (int k0 = 0; k0 < 1024; k0 += 32) {
        __syncthreads();
        for (int i = tid; i < 32 * 32; i += 256) {
            int rr = i >> 5, kk = i & 31;
            qs[rr][kk] = q[(size_t)(b * 128 + rt * 32 + rr) * 1024 + k0 + kk];
        }
        for (int i = tid; i < 64 * 32; i += 256) {
            int rr = i >> 5, kk = i & 31;
            hs[rr][kk] = h[(size_t)(b * 64 + rr) * 1024 + k0 + kk];
        }
        __syncthreads();
#pragma unroll
        for (int kk = 0; kk < 32; ++kk) {
            float qa = qs[r][kk];
#pragma unroll
            for (int j = 0; j < 8; ++j) acc[j] += qa * hs[cg * 8 + j][kk];
        }
    }
    const int row = rt * 32 + r;
    float* op = out + ((size_t)b * 128 + row) * 65;
#pragma unroll
    for (int j = 0; j < 8; ++j) op[1 + cg * 8 + j] = acc[j];
    if (cg == 0) op[0] = 0.f;
}

// ================= host =================
extern "C" void kernel_launch(void* const* d_in, const int* in_sizes, int n_in,
                              void* d_out, int out_size)
{
    const float* x    = (const float*)d_in[0];
    const float* refx = (const float*)d_in[1];
    const float* qW1  = (const float*)d_in[2];
    const float* qb1  = (const float*)d_in[3];
    const float* qW2  = (const float*)d_in[4];
    const float* qb2  = (const float*)d_in[5];
    const float* iW1  = (const float*)d_in[6];
    const float* ib1  = (const float*)d_in[7];
    const float* iW2  = (const float*)d_in[8];
    const float* ib2  = (const float*)d_in[9];
    const float* Wih1 = (const float*)d_in[10];
    const float* Whh1 = (const float*)d_in[11];
    const float* bih1 = (const float*)d_in[12];
    const float* bhh1 = (const float*)d_in[13];
    const float* Wih2 = (const float*)d_in[14];
    const float* Whh2 = (const float*)d_in[15];
    const float* bih2 = (const float*)d_in[16];
    const float* bhh2 = (const float*)d_in[17];
    float* out = (float*)d_out;

    cudaFuncSetAttribute(gemm_l1_sk, cudaFuncAttributeMaxDynamicSharedMemorySize, SMEM_GEMM);
    cudaFuncSetAttribute(mlp_l2,     cudaFuncAttributeMaxDynamicSharedMemorySize, SMEM_GEMM);
    cudaFuncSetAttribute(gemm_xp,    cudaFuncAttributeMaxDynamicSharedMemorySize, SMEM_GEMM);
    cudaFuncSetAttribute(lstm_combo, cudaFuncAttributeMaxDynamicSharedMemorySize, SMEM_GEMM);

#define SYM(v, s) cudaGetSymbolAddress((void**)&v, s)
    bf16 *xh, *xl, *rxh, *rxl, *qW1h, *qW1l, *iW1h, *iW1l, *qW2h, *qW2l, *iW2h, *iW2l;
    bf16 *Wih1h, *Wih1l, *Whh1h, *Whh1l, *Wih2h, *Wih2l, *Whh2h, *Whh2l;
    bf16 *q1h, *q1l, *r1h, *r1l, *rh, *rl, *h1hb, *h1lb, *h2hb, *h2lb;
    float *bs1, *bs2, *q, *xp, *c1, *c2, *h2f, *p0, *p1, *p2, *p3;
    SYM(xh, g_x_h);   SYM(xl, g_x_l);   SYM(rxh, g_rx_h);   SYM(rxl, g_rx_l);
    SYM(qW1h, g_qW1_h); SYM(qW1l, g_qW1_l); SYM(iW1h, g_iW1_h); SYM(iW1l, g_iW1_l);
    SYM(qW2h, g_qW2_h); SYM(qW2l, g_qW2_l); SYM(iW2h, g_iW2_h); SYM(iW2l, g_iW2_l);
    SYM(Wih1h, g_Wih1_h); SYM(Wih1l, g_Wih1_l); SYM(Whh1h, g_Whh1_h); SYM(Whh1l, g_Whh1_l);
    SYM(Wih2h, g_Wih2_h); SYM(Wih2l, g_Wih2_l); SYM(Whh2h, g_Whh2_h); SYM(Whh2l, g_Whh2_l);
    SYM(q1h, g_q1_h); SYM(q1l, g_q1_l); SYM(r1h, g_r1_h); SYM(r1l, g_r1_l);
    SYM(rh, g_r_h);   SYM(rl, g_r_l);
    SYM(h1hb, g_h1_h); SYM(h1lb, g_h1_l); SYM(h2hb, g_h2_h); SYM(h2lb, g_h2_l);
    SYM(bs1, g_bs1); SYM(bs2, g_bs2);
    SYM(q, g_q); SYM(xp, g_xp);
    SYM(c1, g_c1); SYM(c2, g_c2); SYM(h2f, g_h2f);
    SYM(p0, g_p0); SYM(p1, g_p1); SYM(p2, g_p2); SYM(p3, g_p3);
#undef SYM
    const size_t HB = 512u * 1024;
    bf16* h1h[2] = {h1hb, h1hb + HB};
    bf16* h1l[2] = {h1lb, h1lb + HB};
    bf16* h2h[2] = {h2hb, h2hb + HB};
    bf16* h2l[2] = {h2lb, h2lb + HB};

    // ---- splits (biasperm merged into splitperm4 as block 4096) ----
    split_all_k<<<22464, 256>>>(x, xh, xl, qW1, qW1h, qW1l, iW1, iW1h, iW1l,
                                qW2, qW2h, qW2l, iW2, iW2h, iW2l, refx, rxh, rxl);
    splitperm4_k<<<4097, 256>>>(Wih1, Wih1h, Wih1l, Whh1, Whh1h, Whh1l,
                                Wih2, Wih2h, Wih2l, Whh2, Whh2h, Whh2l,
                                bih1, bhh1, bih2, bhh2, bs1, bs2);

    // ---- layer 1: split-K=4 GEMM + combine ----
    gemm_l1_sk<<<dim3(8, 160), 256, SMEM_GEMM>>>(
        xh, xl, qW1h, qW1l, rxh, rxl, iW1h, iW1l, p0, p1, p2, p3);
    combine_l1_k<<<2560, 256>>>(p0, p1, p2, p3, qb1, ib1, q1h, q1l, r1h, r1l);

    // ---- layer 2 (dual region, single pass) ----
    mlp_l2<<<dim3(8, 40), 256, SMEM_GEMM>>>(
        q1h, q1l, qW2h, qW2l, qb2, q, nullptr, nullptr, 8,
        r1h, r1l, iW2h, iW2l, ib2, nullptr, rh, rl);

    // ---- xp = r @ Wih1'^T + bs1 ; t=0 layer-1 cell fused for rows 0..511 ----
    gemm_xp<<<dim3(32, 32), 256, SMEM_GEMM>>>(
        rh, rl, Wih1h, Wih1l, bs1, xp, c1, h1h[0], h1l[0]);

    // ---- LSTM: 7 combo launches + layer2(7) tail ----
    for (int t = 1; t <= 7; ++t) {
        const int pr = (t - 1) & 1, pw = t & 1;
        const int h2r = t & 1, h2w = (t - 1) & 1;
        lstm_combo<<<dim3(32, 8), 256, SMEM_GEMM>>>(
            h1h[pr], h1l[pr],
            Whh1h, Whh1l, xp + (size_t)t * 512 * 4096, c1, h1h[pw], h1l[pw],
            Wih2h, Wih2l,
            (t == 1) ? nullptr : h2h[h2r], (t == 1) ? nullptr : h2l[h2r],
            Whh2h, Whh2l, bs2, c2, h2h[h2w], h2l[h2w], nullptr, (t == 1) ? 1 : 0);
    }
    // tail: layer2(7) — reads h1(7) (parity 1) and h2(6) (parity 0), writes h2(7) + h2f
    lstm_combo<<<dim3(32, 4), 256, SMEM_GEMM>>>(
        h1h[1], h1l[1],
        Whh1h, Whh1l, nullptr, c1, nullptr, nullptr,
        Wih2h, Wih2l, h2h[0], h2l[0],
        Whh2h, Whh2l, bs2, c2, h2h[1], h2l[1], h2f, 0);

    // ---- out ----
    final_k<<<32, 256>>>(q, h2f, out);
}